// round 3
// baseline (speedup 1.0000x reference)
#include <cuda_runtime.h>
#include <cuda_bf16.h>
#include <math_constants.h>
#include <cstdio>

// Problem constants
#define BATCH   2
#define SEQ     2048
#define DMODEL  2048
#define NHEADS  16
#define DHEAD   128
#define MROWS   (BATCH * SEQ)        // 4096
#define QKV_N   (3 * DMODEL)         // 6144

// Scratch (device globals: allocation-free)
__device__ float g_qkv[(size_t)MROWS * QKV_N];     // [4096, 6144]  (q | k | v per row)
__device__ float g_attn[(size_t)MROWS * DMODEL];   // [4096, 2048]  head-concat attention output

// ---------------------------------------------------------------------------
// SGEMM: C[M,N] = A[M,K] @ B[K,N] + bias[N]    (fp32, 128x128x8 tiles, 8x8 uTile)
// ---------------------------------------------------------------------------
#define BM 128
#define BN 128
#define BK 8
#define TM 8
#define TN 8

__global__ __launch_bounds__(256, 2)
void sgemm_bias(int M, int N, int K,
                const float* __restrict__ A,
                const float* __restrict__ B,
                const float* __restrict__ bias,
                float* __restrict__ C)
{
    __shared__ float As[BK][BM];   // A tile, transposed to [k][m]
    __shared__ float Bs[BK][BN];

    const int tid = threadIdx.x;
    const int bm = blockIdx.y * BM;
    const int bn = blockIdx.x * BN;

    // Load mapping: A tile 128x8 -> 256 float4 (2 per row along K)
    const int a_row  = tid >> 1;             // 0..127
    const int a_col4 = (tid & 1) << 2;       // 0 or 4
    // B tile 8x128 -> 256 float4
    const int b_row  = tid >> 5;             // 0..7
    const int b_col4 = (tid & 31) << 2;      // 0..124

    const int tr = (tid >> 4) * TM;          // row in tile
    const int tc = (tid & 15) * TN;          // col in tile

    float acc[TM][TN];
    #pragma unroll
    for (int i = 0; i < TM; i++)
        #pragma unroll
        for (int j = 0; j < TN; j++) acc[i][j] = 0.f;

    const float* Ap = A + (size_t)(bm + a_row) * K + a_col4;
    const float* Bp = B + (size_t)b_row * N + bn + b_col4;

    for (int k0 = 0; k0 < K; k0 += BK) {
        float4 av = *(const float4*)(Ap + k0);
        As[a_col4 + 0][a_row] = av.x;
        As[a_col4 + 1][a_row] = av.y;
        As[a_col4 + 2][a_row] = av.z;
        As[a_col4 + 3][a_row] = av.w;
        *(float4*)&Bs[b_row][b_col4] = *(const float4*)(Bp + (size_t)k0 * N);
        __syncthreads();

        #pragma unroll
        for (int k = 0; k < BK; k++) {
            float4 a0 = *(float4*)&As[k][tr];
            float4 a1 = *(float4*)&As[k][tr + 4];
            float4 b0 = *(float4*)&Bs[k][tc];
            float4 b1 = *(float4*)&Bs[k][tc + 4];
            float ar[TM] = {a0.x, a0.y, a0.z, a0.w, a1.x, a1.y, a1.z, a1.w};
            float br[TN] = {b0.x, b0.y, b0.z, b0.w, b1.x, b1.y, b1.z, b1.w};
            #pragma unroll
            for (int i = 0; i < TM; i++)
                #pragma unroll
                for (int j = 0; j < TN; j++)
                    acc[i][j] += ar[i] * br[j];
        }
        __syncthreads();
    }

    // Epilogue: add bias, vectorized store
    #pragma unroll
    for (int i = 0; i < TM; i++) {
        const size_t row = (size_t)(bm + tr + i);
        #pragma unroll
        for (int j = 0; j < TN; j += 4) {
            const int col = bn + tc + j;
            float4 o;
            o.x = acc[i][j + 0] + bias[col + 0];
            o.y = acc[i][j + 1] + bias[col + 1];
            o.z = acc[i][j + 2] + bias[col + 2];
            o.w = acc[i][j + 3] + bias[col + 3];
            *(float4*)&C[row * N + col] = o;
        }
    }
}

// ---------------------------------------------------------------------------
// Causal flash-attention: per (q-tile of 64, head, batch)
//   Q/K/V read from g_qkv ([4096,6144], col offsets 0 / 2048 / 4096, +h*128)
//   Output written head-concat into g_attn [4096, 2048]
// ---------------------------------------------------------------------------
#define AT_BQ 64
#define AT_BK 64
#define SQ    132   // padded stride for Q/K/V tiles (floats)
#define SSTR  65    // padded stride for score tile

__global__ __launch_bounds__(256, 1)
void attn_kernel(const float* __restrict__ qkv, float* __restrict__ attn_out)
{
    extern __shared__ float sm[];
    float* Qs  = sm;                       // 64*132
    float* KVs = Qs  + AT_BQ * SQ;         // 64*132 (K, then reused for V)
    float* Ss  = KVs + AT_BK * SQ;         // 64*65
    float* m_s = Ss  + AT_BQ * SSTR;       // 64
    float* l_s = m_s + AT_BQ;              // 64
    float* c_s = l_s + AT_BQ;              // 64

    const int tid = threadIdx.x;
    const int q0  = blockIdx.x * AT_BQ;
    const int h   = blockIdx.y;
    const int b   = blockIdx.z;

    const float scale = 0.08838834764831845f;  // 1/sqrt(128)

    // Load Q tile [64][128]
    {
        const float* qbase = qkv + ((size_t)(b * SEQ + q0)) * QKV_N + h * DHEAD;
        for (int i = tid; i < AT_BQ * 32; i += 256) {
            int r  = i >> 5;
            int c4 = (i & 31) << 2;
            *(float4*)&Qs[r * SQ + c4] = *(const float4*)(qbase + (size_t)r * QKV_N + c4);
        }
    }
    if (tid < AT_BQ) { m_s[tid] = -CUDART_INF_F; l_s[tid] = 0.f; }

    const int ty = tid >> 4, tx = tid & 15;
    const int sr = ty * 4;      // S rows (also O rows) owned by this thread
    const int sc = tx * 4;      // S cols
    const int oc = tx * 8;      // O cols

    float o[4][8];
    #pragma unroll
    for (int i = 0; i < 4; i++)
        #pragma unroll
        for (int j = 0; j < 8; j++) o[i][j] = 0.f;

    __syncthreads();

    for (int k0 = 0; k0 <= q0; k0 += AT_BK) {
        // ---- load K tile ----
        {
            const float* kbase = qkv + ((size_t)(b * SEQ + k0)) * QKV_N + DMODEL + h * DHEAD;
            for (int i = tid; i < AT_BK * 32; i += 256) {
                int r = i >> 5; int c4 = (i & 31) << 2;
                *(float4*)&KVs[r * SQ + c4] = *(const float4*)(kbase + (size_t)r * QKV_N + c4);
            }
        }
        __syncthreads();

        // ---- S = Q @ K^T (this thread: 4x4 of the 64x64 tile) ----
        float s[4][4];
        #pragma unroll
        for (int i = 0; i < 4; i++)
            #pragma unroll
            for (int j = 0; j < 4; j++) s[i][j] = 0.f;

        #pragma unroll 4
        for (int k = 0; k < DHEAD; k += 4) {
            float4 qv[4], kv[4];
            #pragma unroll
            for (int i = 0; i < 4; i++) qv[i] = *(float4*)&Qs[(sr + i) * SQ + k];
            #pragma unroll
            for (int j = 0; j < 4; j++) kv[j] = *(float4*)&KVs[(sc + j) * SQ + k];
            #pragma unroll
            for (int i = 0; i < 4; i++)
                #pragma unroll
                for (int j = 0; j < 4; j++) {
                    s[i][j] += qv[i].x * kv[j].x;
                    s[i][j] += qv[i].y * kv[j].y;
                    s[i][j] += qv[i].z * kv[j].z;
                    s[i][j] += qv[i].w * kv[j].w;
                }
        }

        // scale + causal mask, write to Ss
        #pragma unroll
        for (int i = 0; i < 4; i++)
            #pragma unroll
            for (int j = 0; j < 4; j++) {
                float val = s[i][j] * scale;
                if (k0 + sc + j > q0 + sr + i) val = -CUDART_INF_F;
                Ss[(sr + i) * SSTR + sc + j] = val;
            }
        __syncthreads();   // S complete, K tile no longer needed

        // ---- load V tile into the K buffer ----
        {
            const float* vbase = qkv + ((size_t)(b * SEQ + k0)) * QKV_N + 2 * DMODEL + h * DHEAD;
            for (int i = tid; i < AT_BK * 32; i += 256) {
                int r = i >> 5; int c4 = (i & 31) << 2;
                *(float4*)&KVs[r * SQ + c4] = *(const float4*)(vbase + (size_t)r * QKV_N + c4);
            }
        }

        // ---- online softmax (one thread per row) ----
        if (tid < AT_BQ) {
            float* row = &Ss[tid * SSTR];
            float rowmax = -CUDART_INF_F;
            #pragma unroll 8
            for (int c = 0; c < AT_BK; c++) rowmax = fmaxf(rowmax, row[c]);
            const float mprev = m_s[tid];
            const float nm = fmaxf(mprev, rowmax);      // finite: diagonal always present
            const float corr = __expf(mprev - nm);      // 0 on first tile
            float sum = 0.f;
            #pragma unroll 8
            for (int c = 0; c < AT_BK; c++) {
                float p = __expf(row[c] - nm);          // masked -> 0
                row[c] = p;
                sum += p;
            }
            l_s[tid] = l_s[tid] * corr + sum;
            m_s[tid] = nm;
            c_s[tid] = corr;
        }
        __syncthreads();   // P + corr + V all ready

        // ---- rescale O, accumulate O += P @ V ----
        float cr[4];
        #pragma unroll
        for (int i = 0; i < 4; i++) cr[i] = c_s[sr + i];
        #pragma unroll
        for (int i = 0; i < 4; i++)
            #pragma unroll
            for (int j = 0; j < 8; j++) o[i][j] *= cr[i];

        #pragma unroll 4
        for (int kk = 0; kk < AT_BK; kk++) {
            float p[4];
            #pragma unroll
            for (int i = 0; i < 4; i++) p[i] = Ss[(sr + i) * SSTR + kk];
            float4 v0 = *(float4*)&KVs[kk * SQ + oc];
            float4 v1 = *(float4*)&KVs[kk * SQ + oc + 4];
            #pragma unroll
            for (int i = 0; i < 4; i++) {
                o[i][0] += p[i] * v0.x;  o[i][1] += p[i] * v0.y;
                o[i][2] += p[i] * v0.z;  o[i][3] += p[i] * v0.w;
                o[i][4] += p[i] * v1.x;  o[i][5] += p[i] * v1.y;
                o[i][6] += p[i] * v1.z;  o[i][7] += p[i] * v1.w;
            }
        }
        __syncthreads();   // protect KVs/Ss before next iteration
    }

    // ---- epilogue: normalize and write head-concat output ----
    float inv[4];
    #pragma unroll
    for (int i = 0; i < 4; i++) inv[i] = 1.f / l_s[sr + i];

    float* obase = attn_out + ((size_t)(b * SEQ + q0)) * DMODEL + h * DHEAD;
    #pragma unroll
    for (int i = 0; i < 4; i++) {
        float4 r0, r1;
        r0.x = o[i][0] * inv[i]; r0.y = o[i][1] * inv[i];
        r0.z = o[i][2] * inv[i]; r0.w = o[i][3] * inv[i];
        r1.x = o[i][4] * inv[i]; r1.y = o[i][5] * inv[i];
        r1.z = o[i][6] * inv[i]; r1.w = o[i][7] * inv[i];
        *(float4*)&obase[(size_t)(sr + i) * DMODEL + oc]     = r0;
        *(float4*)&obase[(size_t)(sr + i) * DMODEL + oc + 4] = r1;
    }
}

// ---------------------------------------------------------------------------
// Host launcher
// ---------------------------------------------------------------------------
extern "C" void kernel_launch(void* const* d_in, const int* in_sizes, int n_in,
                              void* d_out, int out_size)
{
    (void)in_sizes; (void)n_in; (void)out_size;
    const float* x     = (const float*)d_in[0];
    const float* W_qkv = (const float*)d_in[1];
    const float* b_qkv = (const float*)d_in[2];
    const float* W_out = (const float*)d_in[3];
    const float* b_out = (const float*)d_in[4];
    float* out = (float*)d_out;

    float* qkv_buf = nullptr;
    float* attn_buf = nullptr;
    cudaGetSymbolAddress((void**)&qkv_buf, g_qkv);
    cudaGetSymbolAddress((void**)&attn_buf, g_attn);

    const size_t attn_smem = (size_t)(AT_BQ * SQ + AT_BK * SQ + AT_BQ * SSTR + 3 * AT_BQ) * sizeof(float);
    cudaFuncSetAttribute(attn_kernel, cudaFuncAttributeMaxDynamicSharedMemorySize, (int)attn_smem);

    // 1) QKV projection: [4096,2048] @ [2048,6144] + bias
    {
        dim3 grid(QKV_N / BN, MROWS / BM);
        sgemm_bias<<<grid, 256>>>(MROWS, QKV_N, DMODEL, x, W_qkv, b_qkv, qkv_buf);
    }

    // 2) Causal flash-attention
    {
        dim3 grid(SEQ / AT_BQ, NHEADS, BATCH);   // (32, 16, 2)
        attn_kernel<<<grid, 256, attn_smem>>>(qkv_buf, attn_buf);
    }

    // 3) Output projection: [4096,2048] @ [2048,2048] + bias
    {
        dim3 grid(DMODEL / BN, MROWS / BM);
        sgemm_bias<<<grid, 256>>>(MROWS, DMODEL, DMODEL, attn_buf, W_out, b_out, out);
    }
}

// round 10
// speedup vs baseline: 1.5416x; 1.5416x over previous
#include <cuda_runtime.h>
#include <cuda_bf16.h>
#include <math_constants.h>
#include <cstdint>
#include <cstdio>

// Problem constants
#define BATCH   2
#define SEQ     2048
#define DMODEL  2048
#define NHEADS  16
#define DHEAD   128
#define MROWS   (BATCH * SEQ)        // 4096
#define QKV_N   (3 * DMODEL)         // 6144

// ---------------------------------------------------------------------------
// Scratch (device globals: allocation-free)
// ---------------------------------------------------------------------------
__device__ float g_qkv[(size_t)MROWS * QKV_N];      // [4096, 6144]
__device__ float g_attn[(size_t)MROWS * DMODEL];    // [4096, 2048]
__device__ __nv_bfloat16 g_a_hi[(size_t)MROWS * DMODEL];
__device__ __nv_bfloat16 g_a_lo[(size_t)MROWS * DMODEL];
__device__ __nv_bfloat16 g_wqkv_hi[(size_t)QKV_N * DMODEL];
__device__ __nv_bfloat16 g_wqkv_lo[(size_t)QKV_N * DMODEL];
__device__ __nv_bfloat16 g_wout_hi[(size_t)DMODEL * DMODEL];
__device__ __nv_bfloat16 g_wout_lo[(size_t)DMODEL * DMODEL];

// ---------------------------------------------------------------------------
// PTX helpers (baseline ISA only — no 'a'-feature instructions)
// ---------------------------------------------------------------------------
__device__ __forceinline__ uint32_t smem_u32(const void* p) {
    uint32_t a;
    asm("{ .reg .u64 t; cvta.to.shared.u64 t, %1; cvt.u32.u64 %0, t; }" : "=r"(a) : "l"(p));
    return a;
}
__device__ __forceinline__ void cp16(uint32_t s, const void* g) {
    asm volatile("cp.async.cg.shared.global [%0], [%1], 16;" :: "r"(s), "l"(g));
}
#define CP_COMMIT() asm volatile("cp.async.commit_group;" ::: "memory")
#define CP_WAIT1()  asm volatile("cp.async.wait_group 1;" ::: "memory")
#define CP_WAIT0()  asm volatile("cp.async.wait_group 0;" ::: "memory")

__device__ __forceinline__ void ldsm_x4(uint32_t* r, uint32_t addr) {
    asm volatile("ldmatrix.sync.aligned.m8n8.x4.shared.b16 {%0,%1,%2,%3}, [%4];"
        : "=r"(r[0]), "=r"(r[1]), "=r"(r[2]), "=r"(r[3]) : "r"(addr));
}
__device__ __forceinline__ void mma16816(float* d, const uint32_t* a, const uint32_t* b) {
    asm volatile("mma.sync.aligned.m16n8k16.row.col.f32.bf16.bf16.f32 "
        "{%0,%1,%2,%3}, {%4,%5,%6,%7}, {%8,%9}, {%0,%1,%2,%3};"
        : "+f"(d[0]), "+f"(d[1]), "+f"(d[2]), "+f"(d[3])
        : "r"(a[0]), "r"(a[1]), "r"(a[2]), "r"(a[3]), "r"(b[0]), "r"(b[1]));
}

// ---------------------------------------------------------------------------
// Prep kernels
// ---------------------------------------------------------------------------
__global__ void split_kernel(const float* __restrict__ A, int n,
                             __nv_bfloat16* __restrict__ hi, __nv_bfloat16* __restrict__ lo)
{
    int i = (blockIdx.x * blockDim.x + threadIdx.x) * 4;
    if (i >= n) return;
    float4 v = *(const float4*)&A[i];
    float f[4] = {v.x, v.y, v.z, v.w};
    __nv_bfloat16 h[4], l[4];
    #pragma unroll
    for (int j = 0; j < 4; j++) {
        h[j] = __float2bfloat16(f[j]);
        l[j] = __float2bfloat16(f[j] - __bfloat162float(h[j]));
    }
    *(uint2*)&hi[i] = *(uint2*)h;
    *(uint2*)&lo[i] = *(uint2*)l;
}

// W[K][N] row-major fp32 -> Bhi/Blo[N][K] bf16 (K-major).
__global__ void transpose_split(const float* __restrict__ W, int K, int N,
                                __nv_bfloat16* __restrict__ Bhi, __nv_bfloat16* __restrict__ Blo)
{
    __shared__ float t[32][33];
    int tx = threadIdx.x, ty = threadIdx.y;
    int k = blockIdx.y * 32 + ty;
    int n = blockIdx.x * 32 + tx;
    t[ty][tx] = W[(size_t)k * N + n];
    __syncthreads();
    int n2 = blockIdx.x * 32 + ty;
    int k2 = blockIdx.y * 32 + tx;
    float v = t[tx][ty];
    __nv_bfloat16 h = __float2bfloat16(v);
    __nv_bfloat16 l = __float2bfloat16(v - __bfloat162float(h));
    Bhi[(size_t)n2 * K + k2] = h;
    Blo[(size_t)n2 * K + k2] = l;
}

// ---------------------------------------------------------------------------
// Warp-MMA split-bf16 GEMM: C[M,N] = A[M,K] @ B[N,K]^T + bias
//   128x128 block tile, BK=32, double-buffered cp.async, 8 warps of 64x32.
// ---------------------------------------------------------------------------
#define MT_BM   128
#define MT_BN   128
#define MT_BK   32
#define MT_LDSB 80                    // bytes per smem row (32*2 data + 16 pad)
#define TILEB   (MT_BM * MT_LDSB)     // 10240 bytes per (tile,precision)
#define STAGEB  (4 * TILEB)           // Ahi,Alo,Bhi,Blo = 40960
#define GEMM_SMEM (2 * STAGEB)        // 81920

__global__ __launch_bounds__(256)
void gemm_mma(int M, int N, int K,
              const __nv_bfloat16* __restrict__ Ahi, const __nv_bfloat16* __restrict__ Alo,
              const __nv_bfloat16* __restrict__ Bhi, const __nv_bfloat16* __restrict__ Blo,
              const float* __restrict__ bias, float* __restrict__ C)
{
    extern __shared__ char smem[];
    const uint32_t sbase = smem_u32(smem);
    const int tid  = threadIdx.x;
    const int wid  = tid >> 5;
    const int lane = tid & 31;

    const int bn = blockIdx.x * MT_BN;
    const int bm = blockIdx.y * MT_BM;

    // warp tile: 64(m) x 32(n); warps 2(m) x 4(n)
    const int wm0 = (wid >> 2) * 64;
    const int wn0 = (wid & 3) * 32;

    // ---- cp.async load mapping: row = tid/2, two 16B chunks at (tid&1)*32B ----
    const int lrow = tid >> 1;
    const int lcb  = (tid & 1) * 32;           // byte offset within 64B row data

    const __nv_bfloat16* gA[2] = {Ahi, Alo};
    const __nv_bfloat16* gB[2] = {Bhi, Blo};
    const size_t arow = (size_t)(bm + lrow) * K;
    const size_t brow = (size_t)(bn + lrow) * K;
    const uint32_t srow_off = (uint32_t)lrow * MT_LDSB + lcb;

    // ---- ldmatrix per-lane base addresses (byte offsets within a tile) ----
    // A frag (x4): m = lane%8 + ((lane>>3)&1)*8 ; k-half = lane>>4
    const uint32_t a_off = (uint32_t)(wm0 + (lane & 7) + ((lane >> 3) & 1) * 8) * MT_LDSB
                         + (uint32_t)(lane >> 4) * 16;
    // B frag pair (x4): n = lane%8 + (lane>=16 ? 8:0) ; k-half = (lane>>3)&1
    const uint32_t b_off = (uint32_t)(wn0 + (lane & 7) + ((lane >> 4) & 1) * 8) * MT_LDSB
                         + (uint32_t)((lane >> 3) & 1) * 16;

    float c[4][4][4];
    #pragma unroll
    for (int i = 0; i < 4; i++)
        #pragma unroll
        for (int j = 0; j < 4; j++)
            #pragma unroll
            for (int r = 0; r < 4; r++) c[i][j][r] = 0.f;

    const int nk = K / MT_BK;

    // prologue: stage 0
    {
        const uint32_t st = sbase;
        #pragma unroll
        for (int p = 0; p < 2; p++) {
            const __nv_bfloat16* ga = gA[p] + arow + lcb / 2;
            const __nv_bfloat16* gb = gB[p] + brow + lcb / 2;
            cp16(st + p * TILEB + srow_off,      ga);
            cp16(st + p * TILEB + srow_off + 16, ga + 8);
            cp16(st + (2 + p) * TILEB + srow_off,      gb);
            cp16(st + (2 + p) * TILEB + srow_off + 16, gb + 8);
        }
        CP_COMMIT();
    }

    for (int kt = 0; kt < nk; kt++) {
        const int cur = kt & 1;
        if (kt + 1 < nk) {
            const uint32_t st = sbase + (cur ^ 1) * STAGEB;
            const int kel = (kt + 1) * MT_BK + lcb / 2;
            #pragma unroll
            for (int p = 0; p < 2; p++) {
                const __nv_bfloat16* ga = gA[p] + arow + kel;
                const __nv_bfloat16* gb = gB[p] + brow + kel;
                cp16(st + p * TILEB + srow_off,      ga);
                cp16(st + p * TILEB + srow_off + 16, ga + 8);
                cp16(st + (2 + p) * TILEB + srow_off,      gb);
                cp16(st + (2 + p) * TILEB + srow_off + 16, gb + 8);
            }
            CP_COMMIT();
            CP_WAIT1();
        } else {
            CP_WAIT0();
        }
        __syncthreads();

        const uint32_t st = sbase + cur * STAGEB;
        #pragma unroll
        for (int ks = 0; ks < 2; ks++) {
            const uint32_t kb = (uint32_t)ks * 32;
            // load A hi/lo fragments (4 m-frags each)
            uint32_t ah[4][4], al[4][4];
            #pragma unroll
            for (int i = 0; i < 4; i++) {
                ldsm_x4(ah[i], st + 0 * TILEB + a_off + (uint32_t)i * 16 * MT_LDSB + kb);
                ldsm_x4(al[i], st + 1 * TILEB + a_off + (uint32_t)i * 16 * MT_LDSB + kb);
            }
            #pragma unroll
            for (int jp = 0; jp < 2; jp++) {
                uint32_t bh[4], bl[4];
                ldsm_x4(bh, st + 2 * TILEB + b_off + (uint32_t)jp * 16 * MT_LDSB + kb);
                ldsm_x4(bl, st + 3 * TILEB + b_off + (uint32_t)jp * 16 * MT_LDSB + kb);
                #pragma unroll
                for (int jj = 0; jj < 2; jj++) {
                    const int j = jp * 2 + jj;
                    #pragma unroll
                    for (int i = 0; i < 4; i++) {
                        mma16816(c[i][j], ah[i], bh + jj * 2);
                        mma16816(c[i][j], ah[i], bl + jj * 2);
                        mma16816(c[i][j], al[i], bh + jj * 2);
                    }
                }
            }
        }
        __syncthreads();
    }

    // ---- epilogue: bias + store ----
    #pragma unroll
    for (int i = 0; i < 4; i++) {
        const int row0 = bm + wm0 + i * 16 + (lane >> 2);
        #pragma unroll
        for (int j = 0; j < 4; j++) {
            const int col = bn + wn0 + j * 8 + (lane & 3) * 2;
            const float b0 = bias[col], b1 = bias[col + 1];
            float2 v0 = make_float2(c[i][j][0] + b0, c[i][j][1] + b1);
            float2 v1 = make_float2(c[i][j][2] + b0, c[i][j][3] + b1);
            *(float2*)&C[(size_t)row0 * N + col]       = v0;
            *(float2*)&C[(size_t)(row0 + 8) * N + col] = v1;
        }
    }
}

// ---------------------------------------------------------------------------
// Causal flash-attention (fp32, unchanged — passing since round 0)
// ---------------------------------------------------------------------------
#define AT_BQ 64
#define AT_BK 64
#define SQ    132
#define SSTR  65

__global__ __launch_bounds__(256, 1)
void attn_kernel(const float* __restrict__ qkv, float* __restrict__ attn_out)
{
    extern __shared__ float sm[];
    float* Qs  = sm;
    float* KVs = Qs  + AT_BQ * SQ;
    float* Ss  = KVs + AT_BK * SQ;
    float* m_s = Ss  + AT_BQ * SSTR;
    float* l_s = m_s + AT_BQ;
    float* c_s = l_s + AT_BQ;

    const int tid = threadIdx.x;
    const int q0  = blockIdx.x * AT_BQ;
    const int h   = blockIdx.y;
    const int b   = blockIdx.z;
    const float scale = 0.08838834764831845f;

    {
        const float* qbase = qkv + ((size_t)(b * SEQ + q0)) * QKV_N + h * DHEAD;
        for (int i = tid; i < AT_BQ * 32; i += 256) {
            int r = i >> 5; int c4 = (i & 31) << 2;
            *(float4*)&Qs[r * SQ + c4] = *(const float4*)(qbase + (size_t)r * QKV_N + c4);
        }
    }
    if (tid < AT_BQ) { m_s[tid] = -CUDART_INF_F; l_s[tid] = 0.f; }

    const int ty = tid >> 4, tx = tid & 15;
    const int sr = ty * 4;
    const int sc = tx * 4;
    const int oc = tx * 8;

    float o[4][8];
    #pragma unroll
    for (int i = 0; i < 4; i++)
        #pragma unroll
        for (int j = 0; j < 8; j++) o[i][j] = 0.f;

    __syncthreads();

    for (int k0 = 0; k0 <= q0; k0 += AT_BK) {
        {
            const float* kbase = qkv + ((size_t)(b * SEQ + k0)) * QKV_N + DMODEL + h * DHEAD;
            for (int i = tid; i < AT_BK * 32; i += 256) {
                int r = i >> 5; int c4 = (i & 31) << 2;
                *(float4*)&KVs[r * SQ + c4] = *(const float4*)(kbase + (size_t)r * QKV_N + c4);
            }
        }
        __syncthreads();

        float s[4][4];
        #pragma unroll
        for (int i = 0; i < 4; i++)
            #pragma unroll
            for (int j = 0; j < 4; j++) s[i][j] = 0.f;

        #pragma unroll 4
        for (int k = 0; k < DHEAD; k += 4) {
            float4 qv[4], kv[4];
            #pragma unroll
            for (int i = 0; i < 4; i++) qv[i] = *(float4*)&Qs[(sr + i) * SQ + k];
            #pragma unroll
            for (int j = 0; j < 4; j++) kv[j] = *(float4*)&KVs[(sc + j) * SQ + k];
            #pragma unroll
            for (int i = 0; i < 4; i++)
                #pragma unroll
                for (int j = 0; j < 4; j++) {
                    s[i][j] += qv[i].x * kv[j].x;
                    s[i][j] += qv[i].y * kv[j].y;
                    s[i][j] += qv[i].z * kv[j].z;
                    s[i][j] += qv[i].w * kv[j].w;
                }
        }

        #pragma unroll
        for (int i = 0; i < 4; i++)
            #pragma unroll
            for (int j = 0; j < 4; j++) {
                float val = s[i][j] * scale;
                if (k0 + sc + j > q0 + sr + i) val = -CUDART_INF_F;
                Ss[(sr + i) * SSTR + sc + j] = val;
            }
        __syncthreads();

        {
            const float* vbase = qkv + ((size_t)(b * SEQ + k0)) * QKV_N + 2 * DMODEL + h * DHEAD;
            for (int i = tid; i < AT_BK * 32; i += 256) {
                int r = i >> 5; int c4 = (i & 31) << 2;
                *(float4*)&KVs[r * SQ + c4] = *(const float4*)(vbase + (size_t)r * QKV_N + c4);
            }
        }

        if (tid < AT_BQ) {
            float* row = &Ss[tid * SSTR];
            float rowmax = -CUDART_INF_F;
            #pragma unroll 8
            for (int c = 0; c < AT_BK; c++) rowmax = fmaxf(rowmax, row[c]);
            const float mprev = m_s[tid];
            const float nm = fmaxf(mprev, rowmax);
            const float corr = __expf(mprev - nm);
            float sum = 0.f;
            #pragma unroll 8
            for (int c = 0; c < AT_BK; c++) {
                float p = __expf(row[c] - nm);
                row[c] = p;
                sum += p;
            }
            l_s[tid] = l_s[tid] * corr + sum;
            m_s[tid] = nm;
            c_s[tid] = corr;
        }
        __syncthreads();

        float cr[4];
        #pragma unroll
        for (int i = 0; i < 4; i++) cr[i] = c_s[sr + i];
        #pragma unroll
        for (int i = 0; i < 4; i++)
            #pragma unroll
            for (int j = 0; j < 8; j++) o[i][j] *= cr[i];

        #pragma unroll 4
        for (int kk = 0; kk < AT_BK; kk++) {
            float p[4];
            #pragma unroll
            for (int i = 0; i < 4; i++) p[i] = Ss[(sr + i) * SSTR + kk];
            float4 v0 = *(float4*)&KVs[kk * SQ + oc];
            float4 v1 = *(float4*)&KVs[kk * SQ + oc + 4];
            #pragma unroll
            for (int i = 0; i < 4; i++) {
                o[i][0] += p[i] * v0.x;  o[i][1] += p[i] * v0.y;
                o[i][2] += p[i] * v0.z;  o[i][3] += p[i] * v0.w;
                o[i][4] += p[i] * v1.x;  o[i][5] += p[i] * v1.y;
                o[i][6] += p[i] * v1.z;  o[i][7] += p[i] * v1.w;
            }
        }
        __syncthreads();
    }

    float inv[4];
    #pragma unroll
    for (int i = 0; i < 4; i++) inv[i] = 1.f / l_s[sr + i];

    float* obase = attn_out + ((size_t)(b * SEQ + q0)) * DMODEL + h * DHEAD;
    #pragma unroll
    for (int i = 0; i < 4; i++) {
        float4 r0, r1;
        r0.x = o[i][0] * inv[i]; r0.y = o[i][1] * inv[i];
        r0.z = o[i][2] * inv[i]; r0.w = o[i][3] * inv[i];
        r1.x = o[i][4] * inv[i]; r1.y = o[i][5] * inv[i];
        r1.z = o[i][6] * inv[i]; r1.w = o[i][7] * inv[i];
        *(float4*)&obase[(size_t)(sr + i) * DMODEL + oc]     = r0;
        *(float4*)&obase[(size_t)(sr + i) * DMODEL + oc + 4] = r1;
    }
}

// ---------------------------------------------------------------------------
// Host launcher
// ---------------------------------------------------------------------------
extern "C" void kernel_launch(void* const* d_in, const int* in_sizes, int n_in,
                              void* d_out, int out_size)
{
    (void)in_sizes; (void)n_in; (void)out_size;
    const float* x     = (const float*)d_in[0];
    const float* W_qkv = (const float*)d_in[1];
    const float* b_qkv = (const float*)d_in[2];
    const float* W_out = (const float*)d_in[3];
    const float* b_out = (const float*)d_in[4];
    float* out = (float*)d_out;

    float *qkv_buf, *attn_buf;
    __nv_bfloat16 *ahi, *alo, *wqh, *wql, *woh, *wol;
    cudaGetSymbolAddress((void**)&qkv_buf, g_qkv);
    cudaGetSymbolAddress((void**)&attn_buf, g_attn);
    cudaGetSymbolAddress((void**)&ahi, g_a_hi);
    cudaGetSymbolAddress((void**)&alo, g_a_lo);
    cudaGetSymbolAddress((void**)&wqh, g_wqkv_hi);
    cudaGetSymbolAddress((void**)&wql, g_wqkv_lo);
    cudaGetSymbolAddress((void**)&woh, g_wout_hi);
    cudaGetSymbolAddress((void**)&wol, g_wout_lo);

    static bool attr_set = false;
    const size_t attn_smem = (size_t)(AT_BQ * SQ + AT_BK * SQ + AT_BQ * SSTR + 3 * AT_BQ) * sizeof(float);
    if (!attr_set) {
        cudaFuncSetAttribute(attn_kernel, cudaFuncAttributeMaxDynamicSharedMemorySize, (int)attn_smem);
        cudaFuncSetAttribute(gemm_mma, cudaFuncAttributeMaxDynamicSharedMemorySize, GEMM_SMEM);
        attr_set = true;
    }

    // 0) prep: split x, transpose-split weights
    {
        int n = MROWS * DMODEL;
        split_kernel<<<n / (256 * 4), 256>>>(x, n, ahi, alo);
        dim3 tb(32, 32);
        transpose_split<<<dim3(QKV_N / 32, DMODEL / 32), tb>>>(W_qkv, DMODEL, QKV_N, wqh, wql);
        transpose_split<<<dim3(DMODEL / 32, DMODEL / 32), tb>>>(W_out, DMODEL, DMODEL, woh, wol);
    }

    // 1) QKV projection (warp-MMA split bf16)
    {
        dim3 grid(QKV_N / MT_BN, MROWS / MT_BM);   // (48, 32)
        gemm_mma<<<grid, 256, GEMM_SMEM>>>(MROWS, QKV_N, DMODEL, ahi, alo, wqh, wql, b_qkv, qkv_buf);
    }

    // 2) Causal flash-attention (fp32)
    {
        dim3 grid(SEQ / AT_BQ, NHEADS, BATCH);
        attn_kernel<<<grid, 256, attn_smem>>>(qkv_buf, attn_buf);
    }

    // 3) split attention output, then output projection (warp-MMA)
    {
        int n = MROWS * DMODEL;
        split_kernel<<<n / (256 * 4), 256>>>(attn_buf, n, ahi, alo);
        dim3 grid(DMODEL / MT_BN, MROWS / MT_BM);  // (16, 32)
        gemm_mma<<<grid, 256, GEMM_SMEM>>>(MROWS, DMODEL, DMODEL, ahi, alo, woh, wol, b_out, out);
    }
}

// round 14
// speedup vs baseline: 3.2039x; 2.0783x over previous
#include <cuda_runtime.h>
#include <cuda_bf16.h>
#include <math_constants.h>
#include <cstdint>
#include <cstdio>

// Problem constants
#define BATCH   2
#define SEQ     2048
#define DMODEL  2048
#define NHEADS  16
#define DHEAD   128
#define MROWS   (BATCH * SEQ)        // 4096
#define QKV_N   (3 * DMODEL)         // 6144

// ---------------------------------------------------------------------------
// Scratch (device globals: allocation-free)
// ---------------------------------------------------------------------------
__device__ __nv_bfloat16 g_qkv_hi[(size_t)MROWS * QKV_N];   // [4096, 6144]
__device__ __nv_bfloat16 g_qkv_lo[(size_t)MROWS * QKV_N];
__device__ __nv_bfloat16 g_a_hi[(size_t)MROWS * DMODEL];    // x split, then attn out split
__device__ __nv_bfloat16 g_a_lo[(size_t)MROWS * DMODEL];
__device__ __nv_bfloat16 g_wqkv_hi[(size_t)QKV_N * DMODEL];
__device__ __nv_bfloat16 g_wqkv_lo[(size_t)QKV_N * DMODEL];
__device__ __nv_bfloat16 g_wout_hi[(size_t)DMODEL * DMODEL];
__device__ __nv_bfloat16 g_wout_lo[(size_t)DMODEL * DMODEL];

// ---------------------------------------------------------------------------
// PTX helpers (baseline ISA only)
// ---------------------------------------------------------------------------
__device__ __forceinline__ uint32_t smem_u32(const void* p) {
    uint32_t a;
    asm("{ .reg .u64 t; cvta.to.shared.u64 t, %1; cvt.u32.u64 %0, t; }" : "=r"(a) : "l"(p));
    return a;
}
__device__ __forceinline__ void cp16(uint32_t s, const void* g) {
    asm volatile("cp.async.cg.shared.global [%0], [%1], 16;" :: "r"(s), "l"(g));
}
#define CP_COMMIT() asm volatile("cp.async.commit_group;" ::: "memory")
#define CP_WAIT1()  asm volatile("cp.async.wait_group 1;" ::: "memory")
#define CP_WAIT0()  asm volatile("cp.async.wait_group 0;" ::: "memory")

__device__ __forceinline__ void ldsm_x4(uint32_t* r, uint32_t addr) {
    asm volatile("ldmatrix.sync.aligned.m8n8.x4.shared.b16 {%0,%1,%2,%3}, [%4];"
        : "=r"(r[0]), "=r"(r[1]), "=r"(r[2]), "=r"(r[3]) : "r"(addr));
}
__device__ __forceinline__ void ldsm_x4_t(uint32_t* r, uint32_t addr) {
    asm volatile("ldmatrix.sync.aligned.m8n8.x4.trans.shared.b16 {%0,%1,%2,%3}, [%4];"
        : "=r"(r[0]), "=r"(r[1]), "=r"(r[2]), "=r"(r[3]) : "r"(addr));
}
__device__ __forceinline__ void mma16816(float* d, const uint32_t* a, const uint32_t* b) {
    asm volatile("mma.sync.aligned.m16n8k16.row.col.f32.bf16.bf16.f32 "
        "{%0,%1,%2,%3}, {%4,%5,%6,%7}, {%8,%9}, {%0,%1,%2,%3};"
        : "+f"(d[0]), "+f"(d[1]), "+f"(d[2]), "+f"(d[3])
        : "r"(a[0]), "r"(a[1]), "r"(a[2]), "r"(a[3]), "r"(b[0]), "r"(b[1]));
}

// hi/lo bf16 split of a float pair, packed as bf16x2 (low = first element)
__device__ __forceinline__ void split2(float a, float b, uint32_t& hi, uint32_t& lo) {
    __nv_bfloat16 ha = __float2bfloat16(a);
    __nv_bfloat16 hb = __float2bfloat16(b);
    float la = a - __bfloat162float(ha);
    float lb = b - __bfloat162float(hb);
    __nv_bfloat162 hv; hv.x = ha; hv.y = hb;
    __nv_bfloat162 lv = __floats2bfloat162_rn(la, lb);
    hi = *reinterpret_cast<uint32_t*>(&hv);
    lo = *reinterpret_cast<uint32_t*>(&lv);
}

// ---------------------------------------------------------------------------
// Prep kernels
// ---------------------------------------------------------------------------
__global__ void split_kernel(const float* __restrict__ A, int n,
                             __nv_bfloat16* __restrict__ hi, __nv_bfloat16* __restrict__ lo)
{
    int i = (blockIdx.x * blockDim.x + threadIdx.x) * 4;
    if (i >= n) return;
    float4 v = *(const float4*)&A[i];
    float f[4] = {v.x, v.y, v.z, v.w};
    __nv_bfloat16 h[4], l[4];
    #pragma unroll
    for (int j = 0; j < 4; j++) {
        h[j] = __float2bfloat16(f[j]);
        l[j] = __float2bfloat16(f[j] - __bfloat162float(h[j]));
    }
    *(uint2*)&hi[i] = *(uint2*)h;
    *(uint2*)&lo[i] = *(uint2*)l;
}

// W[K][N] row-major fp32 -> Bhi/Blo[N][K] bf16 (K-major).
__global__ void transpose_split(const float* __restrict__ W, int K, int N,
                                __nv_bfloat16* __restrict__ Bhi, __nv_bfloat16* __restrict__ Blo)
{
    __shared__ float t[32][33];
    int tx = threadIdx.x, ty = threadIdx.y;
    int k = blockIdx.y * 32 + ty;
    int n = blockIdx.x * 32 + tx;
    t[ty][tx] = W[(size_t)k * N + n];
    __syncthreads();
    int n2 = blockIdx.x * 32 + ty;
    int k2 = blockIdx.y * 32 + tx;
    float v = t[tx][ty];
    __nv_bfloat16 h = __float2bfloat16(v);
    __nv_bfloat16 l = __float2bfloat16(v - __bfloat162float(h));
    Bhi[(size_t)n2 * K + k2] = h;
    Blo[(size_t)n2 * K + k2] = l;
}

// ---------------------------------------------------------------------------
// Warp-MMA split-bf16 GEMM: C[M,N] = A[M,K] @ B[N,K]^T + bias
//   OUT_MODE 0: fp32 C     OUT_MODE 1: hi/lo bf16 split output
// ---------------------------------------------------------------------------
#define MT_BM   128
#define MT_BN   128
#define MT_BK   32
#define MT_LDSB 80
#define TILEB   (MT_BM * MT_LDSB)     // 10240
#define STAGEB  (4 * TILEB)           // 40960
#define GEMM_SMEM (2 * STAGEB)        // 81920

template<int OUT_MODE>
__global__ __launch_bounds__(256)
void gemm_mma(int M, int N, int K,
              const __nv_bfloat16* __restrict__ Ahi, const __nv_bfloat16* __restrict__ Alo,
              const __nv_bfloat16* __restrict__ Bhi, const __nv_bfloat16* __restrict__ Blo,
              const float* __restrict__ bias, float* __restrict__ C,
              __nv_bfloat16* __restrict__ Chi, __nv_bfloat16* __restrict__ Clo)
{
    extern __shared__ char smem[];
    const uint32_t sbase = smem_u32(smem);
    const int tid  = threadIdx.x;
    const int wid  = tid >> 5;
    const int lane = tid & 31;

    const int bn = blockIdx.x * MT_BN;
    const int bm = blockIdx.y * MT_BM;

    const int wm0 = (wid >> 2) * 64;
    const int wn0 = (wid & 3) * 32;

    const int lrow = tid >> 1;
    const int lcb  = (tid & 1) * 32;

    const __nv_bfloat16* gA[2] = {Ahi, Alo};
    const __nv_bfloat16* gB[2] = {Bhi, Blo};
    const size_t arow = (size_t)(bm + lrow) * K;
    const size_t brow = (size_t)(bn + lrow) * K;
    const uint32_t srow_off = (uint32_t)lrow * MT_LDSB + lcb;

    const uint32_t a_off = (uint32_t)(wm0 + (lane & 7) + ((lane >> 3) & 1) * 8) * MT_LDSB
                         + (uint32_t)(lane >> 4) * 16;
    const uint32_t b_off = (uint32_t)(wn0 + (lane & 7) + ((lane >> 4) & 1) * 8) * MT_LDSB
                         + (uint32_t)((lane >> 3) & 1) * 16;

    float c[4][4][4];
    #pragma unroll
    for (int i = 0; i < 4; i++)
        #pragma unroll
        for (int j = 0; j < 4; j++)
            #pragma unroll
            for (int r = 0; r < 4; r++) c[i][j][r] = 0.f;

    const int nk = K / MT_BK;

    {
        const uint32_t st = sbase;
        #pragma unroll
        for (int p = 0; p < 2; p++) {
            const __nv_bfloat16* ga = gA[p] + arow + lcb / 2;
            const __nv_bfloat16* gb = gB[p] + brow + lcb / 2;
            cp16(st + p * TILEB + srow_off,      ga);
            cp16(st + p * TILEB + srow_off + 16, ga + 8);
            cp16(st + (2 + p) * TILEB + srow_off,      gb);
            cp16(st + (2 + p) * TILEB + srow_off + 16, gb + 8);
        }
        CP_COMMIT();
    }

    for (int kt = 0; kt < nk; kt++) {
        const int cur = kt & 1;
        if (kt + 1 < nk) {
            const uint32_t st = sbase + (cur ^ 1) * STAGEB;
            const int kel = (kt + 1) * MT_BK + lcb / 2;
            #pragma unroll
            for (int p = 0; p < 2; p++) {
                const __nv_bfloat16* ga = gA[p] + arow + kel;
                const __nv_bfloat16* gb = gB[p] + brow + kel;
                cp16(st + p * TILEB + srow_off,      ga);
                cp16(st + p * TILEB + srow_off + 16, ga + 8);
                cp16(st + (2 + p) * TILEB + srow_off,      gb);
                cp16(st + (2 + p) * TILEB + srow_off + 16, gb + 8);
            }
            CP_COMMIT();
            CP_WAIT1();
        } else {
            CP_WAIT0();
        }
        __syncthreads();

        const uint32_t st = sbase + cur * STAGEB;
        #pragma unroll
        for (int ks = 0; ks < 2; ks++) {
            const uint32_t kb = (uint32_t)ks * 32;
            uint32_t ah[4][4], al[4][4];
            #pragma unroll
            for (int i = 0; i < 4; i++) {
                ldsm_x4(ah[i], st + 0 * TILEB + a_off + (uint32_t)i * 16 * MT_LDSB + kb);
                ldsm_x4(al[i], st + 1 * TILEB + a_off + (uint32_t)i * 16 * MT_LDSB + kb);
            }
            #pragma unroll
            for (int jp = 0; jp < 2; jp++) {
                uint32_t bh[4], bl[4];
                ldsm_x4(bh, st + 2 * TILEB + b_off + (uint32_t)jp * 16 * MT_LDSB + kb);
                ldsm_x4(bl, st + 3 * TILEB + b_off + (uint32_t)jp * 16 * MT_LDSB + kb);
                #pragma unroll
                for (int jj = 0; jj < 2; jj++) {
                    const int j = jp * 2 + jj;
                    #pragma unroll
                    for (int i = 0; i < 4; i++) {
                        mma16816(c[i][j], ah[i], bh + jj * 2);
                        mma16816(c[i][j], ah[i], bl + jj * 2);
                        mma16816(c[i][j], al[i], bh + jj * 2);
                    }
                }
            }
        }
        __syncthreads();
    }

    // ---- epilogue ----
    #pragma unroll
    for (int i = 0; i < 4; i++) {
        const int row0 = bm + wm0 + i * 16 + (lane >> 2);
        #pragma unroll
        for (int j = 0; j < 4; j++) {
            const int col = bn + wn0 + j * 8 + (lane & 3) * 2;
            const float b0 = bias[col], b1 = bias[col + 1];
            const float v00 = c[i][j][0] + b0, v01 = c[i][j][1] + b1;
            const float v10 = c[i][j][2] + b0, v11 = c[i][j][3] + b1;
            if (OUT_MODE == 0) {
                *(float2*)&C[(size_t)row0 * N + col]       = make_float2(v00, v01);
                *(float2*)&C[(size_t)(row0 + 8) * N + col] = make_float2(v10, v11);
            } else {
                uint32_t h, l;
                split2(v00, v01, h, l);
                *(uint32_t*)&Chi[(size_t)row0 * N + col] = h;
                *(uint32_t*)&Clo[(size_t)row0 * N + col] = l;
                split2(v10, v11, h, l);
                *(uint32_t*)&Chi[(size_t)(row0 + 8) * N + col] = h;
                *(uint32_t*)&Clo[(size_t)(row0 + 8) * N + col] = l;
            }
        }
    }
}

// ---------------------------------------------------------------------------
// Tensor-core causal flash-attention (split bf16, FA2 layout)
//   4 warps; warp w owns q rows [16w, 16w+16) of a 64-row q tile.
//   Consumes g_qkv_hi/lo, produces hi/lo split head-concat output.
// ---------------------------------------------------------------------------
#define FA_BQ   64
#define FA_BK   64
#define FA_STR  272                    // smem row stride bytes (256 data + 16 pad)
#define FA_TILE (FA_BQ * FA_STR)       // 17408
#define FA_SMEM (6 * FA_TILE)          // 104448

__global__ __launch_bounds__(128, 2)
void attn_mma(const __nv_bfloat16* __restrict__ qh, const __nv_bfloat16* __restrict__ ql,
              __nv_bfloat16* __restrict__ Ohi, __nv_bfloat16* __restrict__ Olo)
{
    extern __shared__ char smem[];
    const uint32_t sb  = smem_u32(smem);
    const uint32_t sQh = sb,               sQl = sb + FA_TILE;
    const uint32_t sKh = sb + 2 * FA_TILE, sKl = sb + 3 * FA_TILE;
    const uint32_t sVh = sb + 4 * FA_TILE, sVl = sb + 5 * FA_TILE;

    const int tid  = threadIdx.x;
    const int wid  = tid >> 5;
    const int lane = tid & 31;
    const int q0   = blockIdx.x * FA_BQ;
    const int h    = blockIdx.y;
    const int b    = blockIdx.z;
    const float scale = 0.08838834764831845f;   // 1/sqrt(128)

    // ---- stage Q tile (hi+lo) ----
    {
        const size_t qg = (size_t)(b * SEQ + q0) * QKV_N + h * DHEAD;
        #pragma unroll
        for (int i = 0; i < 8; i++) {
            const int cidx = tid + i * 128;
            const int r = cidx >> 4, cc = cidx & 15;
            const size_t g = qg + (size_t)r * QKV_N + cc * 8;
            const uint32_t so = (uint32_t)r * FA_STR + cc * 16;
            cp16(sQh + so, qh + g);
            cp16(sQl + so, ql + g);
        }
        CP_COMMIT();
    }

    const int wm0 = wid * 16;
    // A (Q) fragment address
    const uint32_t a_off = (uint32_t)(wm0 + (lane & 7) + ((lane >> 3) & 1) * 8) * FA_STR
                         + (uint32_t)(lane >> 4) * 16;
    // B (K) fragment address (non-trans)
    const uint32_t b_off = (uint32_t)((lane & 7) + ((lane >> 4) & 1) * 8) * FA_STR
                         + (uint32_t)((lane >> 3) & 1) * 16;
    // B (V) fragment address (trans)
    const uint32_t v_off = (uint32_t)((lane & 7) + ((lane >> 3) & 1) * 8) * FA_STR
                         + (uint32_t)(lane >> 4) * 16;

    float co[16][4];
    #pragma unroll
    for (int t = 0; t < 16; t++)
        #pragma unroll
        for (int e = 0; e < 4; e++) co[t][e] = 0.f;

    float m0 = -CUDART_INF_F, m1 = -CUDART_INF_F;
    float l0 = 0.f, l1 = 0.f;

    const int rowg0 = q0 + wm0 + (lane >> 2);
    const int rowg1 = rowg0 + 8;

    const int nkv = q0 / FA_BK + 1;
    for (int kt = 0; kt < nkv; kt++) {
        const int k0 = kt * FA_BK;
        // ---- stage K,V tiles ----
        {
            const size_t kg = (size_t)(b * SEQ + k0) * QKV_N + DMODEL + h * DHEAD;
            const size_t vg = kg + DMODEL;
            #pragma unroll
            for (int i = 0; i < 8; i++) {
                const int cidx = tid + i * 128;
                const int r = cidx >> 4, cc = cidx & 15;
                const size_t gk = kg + (size_t)r * QKV_N + cc * 8;
                const size_t gv = vg + (size_t)r * QKV_N + cc * 8;
                const uint32_t so = (uint32_t)r * FA_STR + cc * 16;
                cp16(sKh + so, qh + gk);
                cp16(sKl + so, ql + gk);
                cp16(sVh + so, qh + gv);
                cp16(sVl + so, ql + gv);
            }
            CP_COMMIT();
            CP_WAIT0();
            __syncthreads();
        }

        // ---- S = Q K^T (3-product split) ----
        float s[8][4];
        #pragma unroll
        for (int j = 0; j < 8; j++)
            #pragma unroll
            for (int e = 0; e < 4; e++) s[j][e] = 0.f;

        #pragma unroll
        for (int kk = 0; kk < 8; kk++) {
            uint32_t ahf[4], alf[4];
            ldsm_x4(ahf, sQh + a_off + kk * 32);
            ldsm_x4(alf, sQl + a_off + kk * 32);
            #pragma unroll
            for (int jn = 0; jn < 4; jn++) {
                uint32_t bh[4], bl[4];
                ldsm_x4(bh, sKh + b_off + (uint32_t)jn * 16 * FA_STR + kk * 32);
                ldsm_x4(bl, sKl + b_off + (uint32_t)jn * 16 * FA_STR + kk * 32);
                #pragma unroll
                for (int jj = 0; jj < 2; jj++) {
                    float* sc = s[jn * 2 + jj];
                    mma16816(sc, ahf, bh + jj * 2);
                    mma16816(sc, ahf, bl + jj * 2);
                    mma16816(sc, alf, bh + jj * 2);
                }
            }
        }

        // ---- scale + causal mask (diagonal tile only) ----
        const bool diag = (k0 == q0);
        #pragma unroll
        for (int j = 0; j < 8; j++) {
            const int colg = k0 + j * 8 + (lane & 3) * 2;
            #pragma unroll
            for (int e = 0; e < 4; e++) {
                float v = s[j][e] * scale;
                if (diag) {
                    const int cg = colg + (e & 1);
                    const int rg = (e < 2) ? rowg0 : rowg1;
                    if (cg > rg) v = -CUDART_INF_F;
                }
                s[j][e] = v;
            }
        }

        // ---- online softmax (rows r, r+8 per thread; quad reduce) ----
        float rm0 = -CUDART_INF_F, rm1 = -CUDART_INF_F;
        #pragma unroll
        for (int j = 0; j < 8; j++) {
            rm0 = fmaxf(rm0, fmaxf(s[j][0], s[j][1]));
            rm1 = fmaxf(rm1, fmaxf(s[j][2], s[j][3]));
        }
        rm0 = fmaxf(rm0, __shfl_xor_sync(0xFFFFFFFFu, rm0, 1));
        rm0 = fmaxf(rm0, __shfl_xor_sync(0xFFFFFFFFu, rm0, 2));
        rm1 = fmaxf(rm1, __shfl_xor_sync(0xFFFFFFFFu, rm1, 1));
        rm1 = fmaxf(rm1, __shfl_xor_sync(0xFFFFFFFFu, rm1, 2));

        const float nm0 = fmaxf(m0, rm0), nm1 = fmaxf(m1, rm1);
        const float corr0 = __expf(m0 - nm0), corr1 = __expf(m1 - nm1);
        m0 = nm0; m1 = nm1;

        float sum0 = 0.f, sum1 = 0.f;
        #pragma unroll
        for (int j = 0; j < 8; j++) {
            float p0 = __expf(s[j][0] - nm0); s[j][0] = p0; sum0 += p0;
            float p1 = __expf(s[j][1] - nm0); s[j][1] = p1; sum0 += p1;
            float p2 = __expf(s[j][2] - nm1); s[j][2] = p2; sum1 += p2;
            float p3 = __expf(s[j][3] - nm1); s[j][3] = p3; sum1 += p3;
        }
        sum0 += __shfl_xor_sync(0xFFFFFFFFu, sum0, 1);
        sum0 += __shfl_xor_sync(0xFFFFFFFFu, sum0, 2);
        sum1 += __shfl_xor_sync(0xFFFFFFFFu, sum1, 1);
        sum1 += __shfl_xor_sync(0xFFFFFFFFu, sum1, 2);
        l0 = l0 * corr0 + sum0;
        l1 = l1 * corr1 + sum1;

        // ---- rescale O ----
        #pragma unroll
        for (int t = 0; t < 16; t++) {
            co[t][0] *= corr0; co[t][1] *= corr0;
            co[t][2] *= corr1; co[t][3] *= corr1;
        }

        // ---- P -> hi/lo bf16 A-fragments (k-chunks of 16 over kv) ----
        uint32_t ph[4][4], pl[4][4];
        #pragma unroll
        for (int jk = 0; jk < 4; jk++) {
            split2(s[2 * jk][0],     s[2 * jk][1],     ph[jk][0], pl[jk][0]);
            split2(s[2 * jk][2],     s[2 * jk][3],     ph[jk][1], pl[jk][1]);
            split2(s[2 * jk + 1][0], s[2 * jk + 1][1], ph[jk][2], pl[jk][2]);
            split2(s[2 * jk + 1][2], s[2 * jk + 1][3], ph[jk][3], pl[jk][3]);
        }

        // ---- O += P V (3-product split, V via ldmatrix.trans) ----
        #pragma unroll
        for (int jk = 0; jk < 4; jk++) {
            #pragma unroll
            for (int nt = 0; nt < 8; nt++) {
                uint32_t vh[4], vl[4];
                const uint32_t vo = v_off + (uint32_t)jk * 16 * FA_STR + nt * 32;
                ldsm_x4_t(vh, sVh + vo);
                ldsm_x4_t(vl, sVl + vo);
                #pragma unroll
                for (int jj = 0; jj < 2; jj++) {
                    float* oacc = co[nt * 2 + jj];
                    mma16816(oacc, ph[jk], vh + jj * 2);
                    mma16816(oacc, ph[jk], vl + jj * 2);
                    mma16816(oacc, pl[jk], vh + jj * 2);
                }
            }
        }
        __syncthreads();   // protect K/V smem before next tile's loads
    }

    // ---- epilogue: normalize, split to hi/lo, head-concat store ----
    const float il0 = 1.f / l0, il1 = 1.f / l1;
    const size_t obase0 = (size_t)(b * SEQ + rowg0) * DMODEL + h * DHEAD;
    const size_t obase1 = (size_t)(b * SEQ + rowg1) * DMODEL + h * DHEAD;
    #pragma unroll
    for (int t = 0; t < 16; t++) {
        const int col = t * 8 + (lane & 3) * 2;
        uint32_t hpk, lpk;
        split2(co[t][0] * il0, co[t][1] * il0, hpk, lpk);
        *(uint32_t*)&Ohi[obase0 + col] = hpk;
        *(uint32_t*)&Olo[obase0 + col] = lpk;
        split2(co[t][2] * il1, co[t][3] * il1, hpk, lpk);
        *(uint32_t*)&Ohi[obase1 + col] = hpk;
        *(uint32_t*)&Olo[obase1 + col] = lpk;
    }
}

// ---------------------------------------------------------------------------
// Host launcher
// ---------------------------------------------------------------------------
extern "C" void kernel_launch(void* const* d_in, const int* in_sizes, int n_in,
                              void* d_out, int out_size)
{
    (void)in_sizes; (void)n_in; (void)out_size;
    const float* x     = (const float*)d_in[0];
    const float* W_qkv = (const float*)d_in[1];
    const float* b_qkv = (const float*)d_in[2];
    const float* W_out = (const float*)d_in[3];
    const float* b_out = (const float*)d_in[4];
    float* out = (float*)d_out;

    __nv_bfloat16 *qh, *ql, *ahi, *alo, *wqh, *wql, *woh, *wol;
    cudaGetSymbolAddress((void**)&qh,  g_qkv_hi);
    cudaGetSymbolAddress((void**)&ql,  g_qkv_lo);
    cudaGetSymbolAddress((void**)&ahi, g_a_hi);
    cudaGetSymbolAddress((void**)&alo, g_a_lo);
    cudaGetSymbolAddress((void**)&wqh, g_wqkv_hi);
    cudaGetSymbolAddress((void**)&wql, g_wqkv_lo);
    cudaGetSymbolAddress((void**)&woh, g_wout_hi);
    cudaGetSymbolAddress((void**)&wol, g_wout_lo);

    static bool attr_set = false;
    if (!attr_set) {
        cudaFuncSetAttribute(gemm_mma<0>, cudaFuncAttributeMaxDynamicSharedMemorySize, GEMM_SMEM);
        cudaFuncSetAttribute(gemm_mma<1>, cudaFuncAttributeMaxDynamicSharedMemorySize, GEMM_SMEM);
        cudaFuncSetAttribute(attn_mma, cudaFuncAttributeMaxDynamicSharedMemorySize, FA_SMEM);
        attr_set = true;
    }

    // 0) prep: split x, transpose-split weights
    {
        int n = MROWS * DMODEL;
        split_kernel<<<n / (256 * 4), 256>>>(x, n, ahi, alo);
        dim3 tb(32, 32);
        transpose_split<<<dim3(QKV_N / 32, DMODEL / 32), tb>>>(W_qkv, DMODEL, QKV_N, wqh, wql);
        transpose_split<<<dim3(DMODEL / 32, DMODEL / 32), tb>>>(W_out, DMODEL, DMODEL, woh, wol);
    }

    // 1) QKV projection -> hi/lo split output (no fp32 round-trip)
    {
        dim3 grid(QKV_N / MT_BN, MROWS / MT_BM);   // (48, 32)
        gemm_mma<1><<<grid, 256, GEMM_SMEM>>>(MROWS, QKV_N, DMODEL, ahi, alo, wqh, wql,
                                              b_qkv, nullptr, qh, ql);
    }

    // 2) Tensor-core causal flash-attention -> hi/lo split output (reuses ahi/alo)
    {
        dim3 grid(SEQ / FA_BQ, NHEADS, BATCH);     // (32, 16, 2)
        attn_mma<<<grid, 128, FA_SMEM>>>(qh, ql, ahi, alo);
    }

    // 3) Output projection -> fp32 d_out
    {
        dim3 grid(DMODEL / MT_BN, MROWS / MT_BM);  // (16, 32)
        gemm_mma<0><<<grid, 256, GEMM_SMEM>>>(MROWS, DMODEL, DMODEL, ahi, alo, woh, wol,
                                              b_out, out, nullptr, nullptr);
    }
}

// round 17
// speedup vs baseline: 4.4786x; 1.3979x over previous
#include <cuda_runtime.h>
#include <cuda_bf16.h>
#include <cuda_fp16.h>
#include <math_constants.h>
#include <cstdint>
#include <cstdio>

// Problem constants
#define BATCH   2
#define SEQ     2048
#define DMODEL  2048
#define NHEADS  16
#define DHEAD   128
#define MROWS   (BATCH * SEQ)        // 4096
#define QKV_N   (3 * DMODEL)         // 6144

// ---------------------------------------------------------------------------
// Scratch (device globals: allocation-free)
// ---------------------------------------------------------------------------
__device__ __nv_bfloat16 g_qkv_hi[(size_t)MROWS * QKV_N];   // [4096, 6144]
__device__ __nv_bfloat16 g_qkv_lo[(size_t)MROWS * QKV_N];
__device__ __nv_bfloat16 g_a_hi[(size_t)MROWS * DMODEL];    // attn out split
__device__ __nv_bfloat16 g_a_lo[(size_t)MROWS * DMODEL];
__device__ __nv_bfloat16 g_wout_hi[(size_t)DMODEL * DMODEL];
__device__ __nv_bfloat16 g_wout_lo[(size_t)DMODEL * DMODEL];
__device__ __half        g_x_f16[(size_t)MROWS * DMODEL];        // x as fp16
__device__ __half        g_wqkv_f16[(size_t)QKV_N * DMODEL];     // W_qkv^T as fp16 [N,K]

// ---------------------------------------------------------------------------
// PTX helpers (baseline ISA only)
// ---------------------------------------------------------------------------
__device__ __forceinline__ uint32_t smem_u32(const void* p) {
    uint32_t a;
    asm("{ .reg .u64 t; cvta.to.shared.u64 t, %1; cvt.u32.u64 %0, t; }" : "=r"(a) : "l"(p));
    return a;
}
__device__ __forceinline__ void cp16(uint32_t s, const void* g) {
    asm volatile("cp.async.cg.shared.global [%0], [%1], 16;" :: "r"(s), "l"(g));
}
#define CP_COMMIT() asm volatile("cp.async.commit_group;" ::: "memory")
#define CP_WAIT1()  asm volatile("cp.async.wait_group 1;" ::: "memory")
#define CP_WAIT0()  asm volatile("cp.async.wait_group 0;" ::: "memory")

__device__ __forceinline__ void ldsm_x4(uint32_t* r, uint32_t addr) {
    asm volatile("ldmatrix.sync.aligned.m8n8.x4.shared.b16 {%0,%1,%2,%3}, [%4];"
        : "=r"(r[0]), "=r"(r[1]), "=r"(r[2]), "=r"(r[3]) : "r"(addr));
}
__device__ __forceinline__ void ldsm_x4_t(uint32_t* r, uint32_t addr) {
    asm volatile("ldmatrix.sync.aligned.m8n8.x4.trans.shared.b16 {%0,%1,%2,%3}, [%4];"
        : "=r"(r[0]), "=r"(r[1]), "=r"(r[2]), "=r"(r[3]) : "r"(addr));
}
__device__ __forceinline__ void mma16816(float* d, const uint32_t* a, const uint32_t* b) {
    asm volatile("mma.sync.aligned.m16n8k16.row.col.f32.bf16.bf16.f32 "
        "{%0,%1,%2,%3}, {%4,%5,%6,%7}, {%8,%9}, {%0,%1,%2,%3};"
        : "+f"(d[0]), "+f"(d[1]), "+f"(d[2]), "+f"(d[3])
        : "r"(a[0]), "r"(a[1]), "r"(a[2]), "r"(a[3]), "r"(b[0]), "r"(b[1]));
}
__device__ __forceinline__ void mma16816h(float* d, const uint32_t* a, const uint32_t* b) {
    asm volatile("mma.sync.aligned.m16n8k16.row.col.f32.f16.f16.f32 "
        "{%0,%1,%2,%3}, {%4,%5,%6,%7}, {%8,%9}, {%0,%1,%2,%3};"
        : "+f"(d[0]), "+f"(d[1]), "+f"(d[2]), "+f"(d[3])
        : "r"(a[0]), "r"(a[1]), "r"(a[2]), "r"(a[3]), "r"(b[0]), "r"(b[1]));
}

// hi/lo bf16 split of a float pair, packed as bf16x2
__device__ __forceinline__ void split2(float a, float b, uint32_t& hi, uint32_t& lo) {
    __nv_bfloat16 ha = __float2bfloat16(a);
    __nv_bfloat16 hb = __float2bfloat16(b);
    float la = a - __bfloat162float(ha);
    float lb = b - __bfloat162float(hb);
    __nv_bfloat162 hv; hv.x = ha; hv.y = hb;
    __nv_bfloat162 lv = __floats2bfloat162_rn(la, lb);
    hi = *reinterpret_cast<uint32_t*>(&hv);
    lo = *reinterpret_cast<uint32_t*>(&lv);
}

// ---------------------------------------------------------------------------
// Prep kernels
// ---------------------------------------------------------------------------
__global__ void split_kernel(const float* __restrict__ A, int n,
                             __nv_bfloat16* __restrict__ hi, __nv_bfloat16* __restrict__ lo)
{
    int i = (blockIdx.x * blockDim.x + threadIdx.x) * 4;
    if (i >= n) return;
    float4 v = *(const float4*)&A[i];
    float f[4] = {v.x, v.y, v.z, v.w};
    __nv_bfloat16 h[4], l[4];
    #pragma unroll
    for (int j = 0; j < 4; j++) {
        h[j] = __float2bfloat16(f[j]);
        l[j] = __float2bfloat16(f[j] - __bfloat162float(h[j]));
    }
    *(uint2*)&hi[i] = *(uint2*)h;
    *(uint2*)&lo[i] = *(uint2*)l;
}

__global__ void conv_f16(const float* __restrict__ A, int n, __half* __restrict__ out)
{
    int i = (blockIdx.x * blockDim.x + threadIdx.x) * 4;
    if (i >= n) return;
    float4 v = *(const float4*)&A[i];
    __half h[4] = {__float2half(v.x), __float2half(v.y), __float2half(v.z), __float2half(v.w)};
    *(uint2*)&out[i] = *(uint2*)h;
}

// W[K][N] row-major fp32 -> Bt[N][K] fp16 (K-major)
__global__ void transpose_f16(const float* __restrict__ W, int K, int N,
                              __half* __restrict__ Bt)
{
    __shared__ float t[32][33];
    int tx = threadIdx.x, ty = threadIdx.y;
    int k = blockIdx.y * 32 + ty;
    int n = blockIdx.x * 32 + tx;
    t[ty][tx] = W[(size_t)k * N + n];
    __syncthreads();
    int n2 = blockIdx.x * 32 + ty;
    int k2 = blockIdx.y * 32 + tx;
    Bt[(size_t)n2 * K + k2] = __float2half(t[tx][ty]);
}

// W[K][N] row-major fp32 -> Bhi/Blo[N][K] bf16 (K-major)
__global__ void transpose_split(const float* __restrict__ W, int K, int N,
                                __nv_bfloat16* __restrict__ Bhi, __nv_bfloat16* __restrict__ Blo)
{
    __shared__ float t[32][33];
    int tx = threadIdx.x, ty = threadIdx.y;
    int k = blockIdx.y * 32 + ty;
    int n = blockIdx.x * 32 + tx;
    t[ty][tx] = W[(size_t)k * N + n];
    __syncthreads();
    int n2 = blockIdx.x * 32 + ty;
    int k2 = blockIdx.y * 32 + tx;
    float v = t[tx][ty];
    __nv_bfloat16 h = __float2bfloat16(v);
    __nv_bfloat16 l = __float2bfloat16(v - __bfloat162float(h));
    Bhi[(size_t)n2 * K + k2] = h;
    Blo[(size_t)n2 * K + k2] = l;
}

// ---------------------------------------------------------------------------
// fp16 single-product GEMM: C[M,N] = A[M,K] @ B[N,K]^T + bias -> hi/lo bf16 out
//   128x128x64 tiles, 2-stage cp.async, 8 warps of 64x32.
// ---------------------------------------------------------------------------
#define F16_BM   128
#define F16_BN   128
#define F16_BK   64
#define F16_LDSB 144                   // 128B data + 16B pad
#define F16_TILE (F16_BM * F16_LDSB)   // 18432
#define F16_STAGE (2 * F16_TILE)       // 36864 (A + B)
#define F16_SMEM (2 * F16_STAGE)       // 73728

__global__ __launch_bounds__(256)
void gemm_f16(int M, int N, int K,
              const __half* __restrict__ A, const __half* __restrict__ B,
              const float* __restrict__ bias,
              __nv_bfloat16* __restrict__ Chi, __nv_bfloat16* __restrict__ Clo)
{
    extern __shared__ char smem[];
    const uint32_t sbase = smem_u32(smem);
    const int tid  = threadIdx.x;
    const int wid  = tid >> 5;
    const int lane = tid & 31;

    const int bn = blockIdx.x * F16_BN;
    const int bm = blockIdx.y * F16_BM;

    const int wm0 = (wid >> 2) * 64;
    const int wn0 = (wid & 3) * 32;

    // cp.async mapping: row = tid/2, 4 chunks of 16B at (tid&1)*64B
    const int lrow = tid >> 1;
    const int lcb  = (tid & 1) * 64;           // byte offset within 128B row data

    const size_t arow = (size_t)(bm + lrow) * K;
    const size_t brow = (size_t)(bn + lrow) * K;
    const uint32_t srow_off = (uint32_t)lrow * F16_LDSB + lcb;

    const uint32_t a_off = (uint32_t)(wm0 + (lane & 7) + ((lane >> 3) & 1) * 8) * F16_LDSB
                         + (uint32_t)(lane >> 4) * 16;
    const uint32_t b_off = (uint32_t)(wn0 + (lane & 7) + ((lane >> 4) & 1) * 8) * F16_LDSB
                         + (uint32_t)((lane >> 3) & 1) * 16;

    float c[4][4][4];
    #pragma unroll
    for (int i = 0; i < 4; i++)
        #pragma unroll
        for (int j = 0; j < 4; j++)
            #pragma unroll
            for (int r = 0; r < 4; r++) c[i][j][r] = 0.f;

    const int nk = K / F16_BK;

    // prologue: stage 0
    {
        const uint32_t st = sbase;
        const __half* ga = A + arow + lcb / 2;
        const __half* gb = B + brow + lcb / 2;
        #pragma unroll
        for (int cc = 0; cc < 4; cc++) {
            cp16(st + srow_off + cc * 16,            ga + cc * 8);
            cp16(st + F16_TILE + srow_off + cc * 16, gb + cc * 8);
        }
        CP_COMMIT();
    }

    for (int kt = 0; kt < nk; kt++) {
        const int cur = kt & 1;
        if (kt + 1 < nk) {
            const uint32_t st = sbase + (cur ^ 1) * F16_STAGE;
            const int kel = (kt + 1) * F16_BK + lcb / 2;
            const __half* ga = A + arow + kel;
            const __half* gb = B + brow + kel;
            #pragma unroll
            for (int cc = 0; cc < 4; cc++) {
                cp16(st + srow_off + cc * 16,            ga + cc * 8);
                cp16(st + F16_TILE + srow_off + cc * 16, gb + cc * 8);
            }
            CP_COMMIT();
            CP_WAIT1();
        } else {
            CP_WAIT0();
        }
        __syncthreads();

        const uint32_t st = sbase + cur * F16_STAGE;
        #pragma unroll
        for (int ks = 0; ks < 4; ks++) {
            const uint32_t kb = (uint32_t)ks * 32;   // 16 fp16 = 32 bytes
            uint32_t ah[4][4];
            #pragma unroll
            for (int i = 0; i < 4; i++)
                ldsm_x4(ah[i], st + a_off + (uint32_t)i * 16 * F16_LDSB + kb);
            #pragma unroll
            for (int jp = 0; jp < 2; jp++) {
                uint32_t bh[4];
                ldsm_x4(bh, st + F16_TILE + b_off + (uint32_t)jp * 16 * F16_LDSB + kb);
                #pragma unroll
                for (int jj = 0; jj < 2; jj++) {
                    const int j = jp * 2 + jj;
                    #pragma unroll
                    for (int i = 0; i < 4; i++)
                        mma16816h(c[i][j], ah[i], bh + jj * 2);
                }
            }
        }
        __syncthreads();
    }

    // epilogue: bias, split to hi/lo bf16
    #pragma unroll
    for (int i = 0; i < 4; i++) {
        const int row0 = bm + wm0 + i * 16 + (lane >> 2);
        #pragma unroll
        for (int j = 0; j < 4; j++) {
            const int col = bn + wn0 + j * 8 + (lane & 3) * 2;
            const float b0 = bias[col], b1 = bias[col + 1];
            uint32_t h, l;
            split2(c[i][j][0] + b0, c[i][j][1] + b1, h, l);
            *(uint32_t*)&Chi[(size_t)row0 * N + col] = h;
            *(uint32_t*)&Clo[(size_t)row0 * N + col] = l;
            split2(c[i][j][2] + b0, c[i][j][3] + b1, h, l);
            *(uint32_t*)&Chi[(size_t)(row0 + 8) * N + col] = h;
            *(uint32_t*)&Clo[(size_t)(row0 + 8) * N + col] = l;
        }
    }
}

// ---------------------------------------------------------------------------
// bf16 3-product GEMM (out projection): C fp32 = A @ B^T + bias
// ---------------------------------------------------------------------------
#define MT_BM   128
#define MT_BN   128
#define MT_BK   32
#define MT_LDSB 80
#define TILEB   (MT_BM * MT_LDSB)     // 10240
#define STAGEB  (4 * TILEB)           // 40960
#define GEMM_SMEM (2 * STAGEB)        // 81920

__global__ __launch_bounds__(256)
void gemm_mma(int M, int N, int K,
              const __nv_bfloat16* __restrict__ Ahi, const __nv_bfloat16* __restrict__ Alo,
              const __nv_bfloat16* __restrict__ Bhi, const __nv_bfloat16* __restrict__ Blo,
              const float* __restrict__ bias, float* __restrict__ C)
{
    extern __shared__ char smem[];
    const uint32_t sbase = smem_u32(smem);
    const int tid  = threadIdx.x;
    const int wid  = tid >> 5;
    const int lane = tid & 31;

    const int bn = blockIdx.x * MT_BN;
    const int bm = blockIdx.y * MT_BM;

    const int wm0 = (wid >> 2) * 64;
    const int wn0 = (wid & 3) * 32;

    const int lrow = tid >> 1;
    const int lcb  = (tid & 1) * 32;

    const __nv_bfloat16* gA[2] = {Ahi, Alo};
    const __nv_bfloat16* gB[2] = {Bhi, Blo};
    const size_t arow = (size_t)(bm + lrow) * K;
    const size_t brow = (size_t)(bn + lrow) * K;
    const uint32_t srow_off = (uint32_t)lrow * MT_LDSB + lcb;

    const uint32_t a_off = (uint32_t)(wm0 + (lane & 7) + ((lane >> 3) & 1) * 8) * MT_LDSB
                         + (uint32_t)(lane >> 4) * 16;
    const uint32_t b_off = (uint32_t)(wn0 + (lane & 7) + ((lane >> 4) & 1) * 8) * MT_LDSB
                         + (uint32_t)((lane >> 3) & 1) * 16;

    float c[4][4][4];
    #pragma unroll
    for (int i = 0; i < 4; i++)
        #pragma unroll
        for (int j = 0; j < 4; j++)
            #pragma unroll
            for (int r = 0; r < 4; r++) c[i][j][r] = 0.f;

    const int nk = K / MT_BK;

    {
        const uint32_t st = sbase;
        #pragma unroll
        for (int p = 0; p < 2; p++) {
            const __nv_bfloat16* ga = gA[p] + arow + lcb / 2;
            const __nv_bfloat16* gb = gB[p] + brow + lcb / 2;
            cp16(st + p * TILEB + srow_off,      ga);
            cp16(st + p * TILEB + srow_off + 16, ga + 8);
            cp16(st + (2 + p) * TILEB + srow_off,      gb);
            cp16(st + (2 + p) * TILEB + srow_off + 16, gb + 8);
        }
        CP_COMMIT();
    }

    for (int kt = 0; kt < nk; kt++) {
        const int cur = kt & 1;
        if (kt + 1 < nk) {
            const uint32_t st = sbase + (cur ^ 1) * STAGEB;
            const int kel = (kt + 1) * MT_BK + lcb / 2;
            #pragma unroll
            for (int p = 0; p < 2; p++) {
                const __nv_bfloat16* ga = gA[p] + arow + kel;
                const __nv_bfloat16* gb = gB[p] + brow + kel;
                cp16(st + p * TILEB + srow_off,      ga);
                cp16(st + p * TILEB + srow_off + 16, ga + 8);
                cp16(st + (2 + p) * TILEB + srow_off,      gb);
                cp16(st + (2 + p) * TILEB + srow_off + 16, gb + 8);
            }
            CP_COMMIT();
            CP_WAIT1();
        } else {
            CP_WAIT0();
        }
        __syncthreads();

        const uint32_t st = sbase + cur * STAGEB;
        #pragma unroll
        for (int ks = 0; ks < 2; ks++) {
            const uint32_t kb = (uint32_t)ks * 32;
            uint32_t ah[4][4], al[4][4];
            #pragma unroll
            for (int i = 0; i < 4; i++) {
                ldsm_x4(ah[i], st + 0 * TILEB + a_off + (uint32_t)i * 16 * MT_LDSB + kb);
                ldsm_x4(al[i], st + 1 * TILEB + a_off + (uint32_t)i * 16 * MT_LDSB + kb);
            }
            #pragma unroll
            for (int jp = 0; jp < 2; jp++) {
                uint32_t bh[4], bl[4];
                ldsm_x4(bh, st + 2 * TILEB + b_off + (uint32_t)jp * 16 * MT_LDSB + kb);
                ldsm_x4(bl, st + 3 * TILEB + b_off + (uint32_t)jp * 16 * MT_LDSB + kb);
                #pragma unroll
                for (int jj = 0; jj < 2; jj++) {
                    const int j = jp * 2 + jj;
                    #pragma unroll
                    for (int i = 0; i < 4; i++) {
                        mma16816(c[i][j], ah[i], bh + jj * 2);
                        mma16816(c[i][j], ah[i], bl + jj * 2);
                        mma16816(c[i][j], al[i], bh + jj * 2);
                    }
                }
            }
        }
        __syncthreads();
    }

    #pragma unroll
    for (int i = 0; i < 4; i++) {
        const int row0 = bm + wm0 + i * 16 + (lane >> 2);
        #pragma unroll
        for (int j = 0; j < 4; j++) {
            const int col = bn + wn0 + j * 8 + (lane & 3) * 2;
            const float b0 = bias[col], b1 = bias[col + 1];
            *(float2*)&C[(size_t)row0 * N + col] =
                make_float2(c[i][j][0] + b0, c[i][j][1] + b1);
            *(float2*)&C[(size_t)(row0 + 8) * N + col] =
                make_float2(c[i][j][2] + b0, c[i][j][3] + b1);
        }
    }
}

// ---------------------------------------------------------------------------
// Tensor-core causal flash-attention (split bf16, FA2 layout) — unchanged
// ---------------------------------------------------------------------------
#define FA_BQ   64
#define FA_BK   64
#define FA_STR  272
#define FA_TILE (FA_BQ * FA_STR)       // 17408
#define FA_SMEM (6 * FA_TILE)          // 104448

__global__ __launch_bounds__(128, 2)
void attn_mma(const __nv_bfloat16* __restrict__ qh, const __nv_bfloat16* __restrict__ ql,
              __nv_bfloat16* __restrict__ Ohi, __nv_bfloat16* __restrict__ Olo)
{
    extern __shared__ char smem[];
    const uint32_t sb  = smem_u32(smem);
    const uint32_t sQh = sb,               sQl = sb + FA_TILE;
    const uint32_t sKh = sb + 2 * FA_TILE, sKl = sb + 3 * FA_TILE;
    const uint32_t sVh = sb + 4 * FA_TILE, sVl = sb + 5 * FA_TILE;

    const int tid  = threadIdx.x;
    const int wid  = tid >> 5;
    const int lane = tid & 31;
    const int q0   = blockIdx.x * FA_BQ;
    const int h    = blockIdx.y;
    const int b    = blockIdx.z;
    const float scale = 0.08838834764831845f;

    {
        const size_t qg = (size_t)(b * SEQ + q0) * QKV_N + h * DHEAD;
        #pragma unroll
        for (int i = 0; i < 8; i++) {
            const int cidx = tid + i * 128;
            const int r = cidx >> 4, cc = cidx & 15;
            const size_t g = qg + (size_t)r * QKV_N + cc * 8;
            const uint32_t so = (uint32_t)r * FA_STR + cc * 16;
            cp16(sQh + so, qh + g);
            cp16(sQl + so, ql + g);
        }
        CP_COMMIT();
    }

    const int wm0 = wid * 16;
    const uint32_t a_off = (uint32_t)(wm0 + (lane & 7) + ((lane >> 3) & 1) * 8) * FA_STR
                         + (uint32_t)(lane >> 4) * 16;
    const uint32_t b_off = (uint32_t)((lane & 7) + ((lane >> 4) & 1) * 8) * FA_STR
                         + (uint32_t)((lane >> 3) & 1) * 16;
    const uint32_t v_off = (uint32_t)((lane & 7) + ((lane >> 3) & 1) * 8) * FA_STR
                         + (uint32_t)(lane >> 4) * 16;

    float co[16][4];
    #pragma unroll
    for (int t = 0; t < 16; t++)
        #pragma unroll
        for (int e = 0; e < 4; e++) co[t][e] = 0.f;

    float m0 = -CUDART_INF_F, m1 = -CUDART_INF_F;
    float l0 = 0.f, l1 = 0.f;

    const int rowg0 = q0 + wm0 + (lane >> 2);
    const int rowg1 = rowg0 + 8;

    const int nkv = q0 / FA_BK + 1;
    for (int kt = 0; kt < nkv; kt++) {
        const int k0 = kt * FA_BK;
        {
            const size_t kg = (size_t)(b * SEQ + k0) * QKV_N + DMODEL + h * DHEAD;
            const size_t vg = kg + DMODEL;
            #pragma unroll
            for (int i = 0; i < 8; i++) {
                const int cidx = tid + i * 128;
                const int r = cidx >> 4, cc = cidx & 15;
                const size_t gk = kg + (size_t)r * QKV_N + cc * 8;
                const size_t gv = vg + (size_t)r * QKV_N + cc * 8;
                const uint32_t so = (uint32_t)r * FA_STR + cc * 16;
                cp16(sKh + so, qh + gk);
                cp16(sKl + so, ql + gk);
                cp16(sVh + so, qh + gv);
                cp16(sVl + so, ql + gv);
            }
            CP_COMMIT();
            CP_WAIT0();
            __syncthreads();
        }

        float s[8][4];
        #pragma unroll
        for (int j = 0; j < 8; j++)
            #pragma unroll
            for (int e = 0; e < 4; e++) s[j][e] = 0.f;

        #pragma unroll
        for (int kk = 0; kk < 8; kk++) {
            uint32_t ahf[4], alf[4];
            ldsm_x4(ahf, sQh + a_off + kk * 32);
            ldsm_x4(alf, sQl + a_off + kk * 32);
            #pragma unroll
            for (int jn = 0; jn < 4; jn++) {
                uint32_t bh[4], bl[4];
                ldsm_x4(bh, sKh + b_off + (uint32_t)jn * 16 * FA_STR + kk * 32);
                ldsm_x4(bl, sKl + b_off + (uint32_t)jn * 16 * FA_STR + kk * 32);
                #pragma unroll
                for (int jj = 0; jj < 2; jj++) {
                    float* sc = s[jn * 2 + jj];
                    mma16816(sc, ahf, bh + jj * 2);
                    mma16816(sc, ahf, bl + jj * 2);
                    mma16816(sc, alf, bh + jj * 2);
                }
            }
        }

        const bool diag = (k0 == q0);
        #pragma unroll
        for (int j = 0; j < 8; j++) {
            const int colg = k0 + j * 8 + (lane & 3) * 2;
            #pragma unroll
            for (int e = 0; e < 4; e++) {
                float v = s[j][e] * scale;
                if (diag) {
                    const int cg = colg + (e & 1);
                    const int rg = (e < 2) ? rowg0 : rowg1;
                    if (cg > rg) v = -CUDART_INF_F;
                }
                s[j][e] = v;
            }
        }

        float rm0 = -CUDART_INF_F, rm1 = -CUDART_INF_F;
        #pragma unroll
        for (int j = 0; j < 8; j++) {
            rm0 = fmaxf(rm0, fmaxf(s[j][0], s[j][1]));
            rm1 = fmaxf(rm1, fmaxf(s[j][2], s[j][3]));
        }
        rm0 = fmaxf(rm0, __shfl_xor_sync(0xFFFFFFFFu, rm0, 1));
        rm0 = fmaxf(rm0, __shfl_xor_sync(0xFFFFFFFFu, rm0, 2));
        rm1 = fmaxf(rm1, __shfl_xor_sync(0xFFFFFFFFu, rm1, 1));
        rm1 = fmaxf(rm1, __shfl_xor_sync(0xFFFFFFFFu, rm1, 2));

        const float nm0 = fmaxf(m0, rm0), nm1 = fmaxf(m1, rm1);
        const float corr0 = __expf(m0 - nm0), corr1 = __expf(m1 - nm1);
        m0 = nm0; m1 = nm1;

        float sum0 = 0.f, sum1 = 0.f;
        #pragma unroll
        for (int j = 0; j < 8; j++) {
            float p0 = __expf(s[j][0] - nm0); s[j][0] = p0; sum0 += p0;
            float p1 = __expf(s[j][1] - nm0); s[j][1] = p1; sum0 += p1;
            float p2 = __expf(s[j][2] - nm1); s[j][2] = p2; sum1 += p2;
            float p3 = __expf(s[j][3] - nm1); s[j][3] = p3; sum1 += p3;
        }
        sum0 += __shfl_xor_sync(0xFFFFFFFFu, sum0, 1);
        sum0 += __shfl_xor_sync(0xFFFFFFFFu, sum0, 2);
        sum1 += __shfl_xor_sync(0xFFFFFFFFu, sum1, 1);
        sum1 += __shfl_xor_sync(0xFFFFFFFFu, sum1, 2);
        l0 = l0 * corr0 + sum0;
        l1 = l1 * corr1 + sum1;

        #pragma unroll
        for (int t = 0; t < 16; t++) {
            co[t][0] *= corr0; co[t][1] *= corr0;
            co[t][2] *= corr1; co[t][3] *= corr1;
        }

        uint32_t ph[4][4], pl[4][4];
        #pragma unroll
        for (int jk = 0; jk < 4; jk++) {
            split2(s[2 * jk][0],     s[2 * jk][1],     ph[jk][0], pl[jk][0]);
            split2(s[2 * jk][2],     s[2 * jk][3],     ph[jk][1], pl[jk][1]);
            split2(s[2 * jk + 1][0], s[2 * jk + 1][1], ph[jk][2], pl[jk][2]);
            split2(s[2 * jk + 1][2], s[2 * jk + 1][3], ph[jk][3], pl[jk][3]);
        }

        #pragma unroll
        for (int jk = 0; jk < 4; jk++) {
            #pragma unroll
            for (int nt = 0; nt < 8; nt++) {
                uint32_t vh[4], vl[4];
                const uint32_t vo = v_off + (uint32_t)jk * 16 * FA_STR + nt * 32;
                ldsm_x4_t(vh, sVh + vo);
                ldsm_x4_t(vl, sVl + vo);
                #pragma unroll
                for (int jj = 0; jj < 2; jj++) {
                    float* oacc = co[nt * 2 + jj];
                    mma16816(oacc, ph[jk], vh + jj * 2);
                    mma16816(oacc, ph[jk], vl + jj * 2);
                    mma16816(oacc, pl[jk], vh + jj * 2);
                }
            }
        }
        __syncthreads();
    }

    const float il0 = 1.f / l0, il1 = 1.f / l1;
    const size_t obase0 = (size_t)(b * SEQ + rowg0) * DMODEL + h * DHEAD;
    const size_t obase1 = (size_t)(b * SEQ + rowg1) * DMODEL + h * DHEAD;
    #pragma unroll
    for (int t = 0; t < 16; t++) {
        const int col = t * 8 + (lane & 3) * 2;
        uint32_t hpk, lpk;
        split2(co[t][0] * il0, co[t][1] * il0, hpk, lpk);
        *(uint32_t*)&Ohi[obase0 + col] = hpk;
        *(uint32_t*)&Olo[obase0 + col] = lpk;
        split2(co[t][2] * il1, co[t][3] * il1, hpk, lpk);
        *(uint32_t*)&Ohi[obase1 + col] = hpk;
        *(uint32_t*)&Olo[obase1 + col] = lpk;
    }
}

// ---------------------------------------------------------------------------
// Host launcher
// ---------------------------------------------------------------------------
extern "C" void kernel_launch(void* const* d_in, const int* in_sizes, int n_in,
                              void* d_out, int out_size)
{
    (void)in_sizes; (void)n_in; (void)out_size;
    const float* x     = (const float*)d_in[0];
    const float* W_qkv = (const float*)d_in[1];
    const float* b_qkv = (const float*)d_in[2];
    const float* W_out = (const float*)d_in[3];
    const float* b_out = (const float*)d_in[4];
    float* out = (float*)d_out;

    __nv_bfloat16 *qh, *ql, *ahi, *alo, *woh, *wol;
    __half *xf, *wqf;
    cudaGetSymbolAddress((void**)&qh,  g_qkv_hi);
    cudaGetSymbolAddress((void**)&ql,  g_qkv_lo);
    cudaGetSymbolAddress((void**)&ahi, g_a_hi);
    cudaGetSymbolAddress((void**)&alo, g_a_lo);
    cudaGetSymbolAddress((void**)&woh, g_wout_hi);
    cudaGetSymbolAddress((void**)&wol, g_wout_lo);
    cudaGetSymbolAddress((void**)&xf,  g_x_f16);
    cudaGetSymbolAddress((void**)&wqf, g_wqkv_f16);

    static bool attr_set = false;
    if (!attr_set) {
        cudaFuncSetAttribute(gemm_f16, cudaFuncAttributeMaxDynamicSharedMemorySize, F16_SMEM);
        cudaFuncSetAttribute(gemm_mma, cudaFuncAttributeMaxDynamicSharedMemorySize, GEMM_SMEM);
        cudaFuncSetAttribute(attn_mma, cudaFuncAttributeMaxDynamicSharedMemorySize, FA_SMEM);
        attr_set = true;
    }

    // 0) prep: x -> fp16, W_qkv -> fp16 [N,K], W_out -> bf16 hi/lo [N,K]
    {
        int n = MROWS * DMODEL;
        conv_f16<<<n / (256 * 4), 256>>>(x, n, xf);
        dim3 tb(32, 32);
        transpose_f16<<<dim3(QKV_N / 32, DMODEL / 32), tb>>>(W_qkv, DMODEL, QKV_N, wqf);
        transpose_split<<<dim3(DMODEL / 32, DMODEL / 32), tb>>>(W_out, DMODEL, DMODEL, woh, wol);
    }

    // 1) QKV projection: fp16 single-product -> hi/lo bf16 split output
    {
        dim3 grid(QKV_N / F16_BN, MROWS / F16_BM);   // (48, 32)
        gemm_f16<<<grid, 256, F16_SMEM>>>(MROWS, QKV_N, DMODEL, xf, wqf, b_qkv, qh, ql);
    }

    // 2) Tensor-core causal flash-attention (3-product bf16)
    {
        dim3 grid(SEQ / FA_BQ, NHEADS, BATCH);       // (32, 16, 2)
        attn_mma<<<grid, 128, FA_SMEM>>>(qh, ql, ahi, alo);
    }

    // 3) Output projection: 3-product bf16 -> fp32 d_out
    {
        dim3 grid(DMODEL / MT_BN, MROWS / MT_BM);    // (16, 32)
        gemm_mma<<<grid, 256, GEMM_SMEM>>>(MROWS, DMODEL, DMODEL, ahi, alo, woh, wol, b_out, out);
    }
}